// round 1
// baseline (speedup 1.0000x reference)
#include <cuda_runtime.h>
#include <math.h>

#define B_  8192
#define D_  256
#define M_  10
#define H_  4
#define DK_ 64

// ---------------- scratch (device globals; no allocation allowed) ----------
__device__ float g_z   [B_*D_];        // z_t
__device__ float g_xp  [B_*3*D_];      // z_t @ gru_k + b0
__device__ float g_hp  [B_*3*D_];      // h_prev @ gru_rk + b1
__device__ float g_gru [B_*D_];        // gru_out
__device__ float g_q   [B_*D_];        // q
__device__ float g_k   [B_*M_*D_];     // k (81920 x 256)
__device__ float g_v   [B_*M_*D_];     // v
__device__ float g_ctxh[B_*D_];        // attention context heads
__device__ float g_ctx [B_*D_];        // context (pre/post LN, in place)
__device__ float g_ctxp[B_*D_];        // tanh(ctx_ln @ W_ctx + b)
__device__ float g_alph[B_*D_];        // gate

__device__ __forceinline__ float sigf(float x) { return 1.0f / (1.0f + expf(-x)); }

// ---------------- generic fp32 SGEMM: C = epi(A @ W + bias) ----------------
// A: (Mrows x K) row-major (if DUAL: A covers cols [0,256), A2 cols [256,K))
// W: (K x N) row-major, bias: (N), C: row stride ldc
// EPI: 0 = identity, 1 = tanh, 2 = sigmoid
template<int EPI, bool DUAL>
__global__ void gemm_kernel(const float* __restrict__ A, const float* __restrict__ A2,
                            const float* __restrict__ W, const float* __restrict__ bias,
                            float* __restrict__ C, int N, int K, int ldc)
{
    const int BM = 64, BN = 64, BK = 16;
    __shared__ float As[BK][BM + 4];
    __shared__ float Bs[BK][BN + 4];

    const int bm  = blockIdx.y * BM;
    const int bn  = blockIdx.x * BN;
    const int tid = threadIdx.x;          // 256 threads
    const int tx  = tid & 15;
    const int ty  = tid >> 4;

    float acc[4][4] = {};

    for (int k0 = 0; k0 < K; k0 += BK) {
        // load A tile (64 rows x 16 k) -> As[k][m]
        #pragma unroll
        for (int i = 0; i < 4; i++) {
            int l = tid + i * 256;
            int r = l >> 4, c = l & 15;
            int gk = k0 + c;
            float av;
            if (DUAL) {
                av = (gk < 256) ? A [(size_t)(bm + r) * 256 + gk]
                                : A2[(size_t)(bm + r) * 256 + gk - 256];
            } else {
                av = A[(size_t)(bm + r) * K + gk];
            }
            As[c][r] = av;
        }
        // load W tile (16 k x 64 n) -> Bs[k][n]
        #pragma unroll
        for (int i = 0; i < 4; i++) {
            int l = tid + i * 256;
            int r = l >> 6, c = l & 63;
            Bs[r][c] = W[(size_t)(k0 + r) * N + bn + c];
        }
        __syncthreads();

        #pragma unroll
        for (int kk = 0; kk < BK; kk++) {
            float4 a4 = *(const float4*)&As[kk][ty * 4];
            float4 b4 = *(const float4*)&Bs[kk][tx * 4];
            float a[4] = {a4.x, a4.y, a4.z, a4.w};
            float b[4] = {b4.x, b4.y, b4.z, b4.w};
            #pragma unroll
            for (int i = 0; i < 4; i++)
                #pragma unroll
                for (int j = 0; j < 4; j++)
                    acc[i][j] += a[i] * b[j];
        }
        __syncthreads();
    }

    #pragma unroll
    for (int i = 0; i < 4; i++) {
        int row = bm + ty * 4 + i;
        #pragma unroll
        for (int j = 0; j < 4; j++) {
            int col = bn + tx * 4 + j;
            float v = acc[i][j] + bias[col];
            if (EPI == 1) v = tanhf(v);
            if (EPI == 2) v = sigf(v);
            C[(size_t)row * ldc + col] = v;
        }
    }
}

// ---------------- GRU elementwise (keras reset_after=True) -----------------
__global__ void gru_kernel(const float* __restrict__ h_prev)
{
    int idx = blockIdx.x * blockDim.x + threadIdx.x;
    if (idx >= B_ * D_) return;
    int b = idx >> 8, d = idx & 255;
    const float* xp = g_xp + (size_t)b * 768;
    const float* hp = g_hp + (size_t)b * 768;
    float z  = sigf(xp[d]       + hp[d]);
    float r  = sigf(xp[256 + d] + hp[256 + d]);
    float hc = tanhf(xp[512 + d] + r * hp[512 + d]);
    float h  = h_prev[idx];
    g_gru[idx] = z * h + (1.0f - z) * hc;
}

// ---------------- attention: one warp per (b, h) ----------------------------
__global__ void attn_kernel()
{
    int gw   = (blockIdx.x * blockDim.x + threadIdx.x) >> 5;
    int lane = threadIdx.x & 31;
    if (gw >= B_ * H_) return;
    int b = gw >> 2;          // / H_
    int h = gw & 3;           // % H_

    const float* qp = g_q + (size_t)b * D_ + h * DK_;
    float q0 = qp[2 * lane], q1 = qp[2 * lane + 1];

    float sc[M_];
    #pragma unroll
    for (int m = 0; m < M_; m++) {
        const float* kp = g_k + ((size_t)b * M_ + m) * D_ + h * DK_;
        float p = q0 * kp[2 * lane] + q1 * kp[2 * lane + 1];
        #pragma unroll
        for (int o = 16; o > 0; o >>= 1) p += __shfl_xor_sync(0xffffffffu, p, o);
        sc[m] = p * 0.125f;   // 1/sqrt(64)
    }
    float mx = sc[0];
    #pragma unroll
    for (int m = 1; m < M_; m++) mx = fmaxf(mx, sc[m]);
    float sum = 0.0f;
    #pragma unroll
    for (int m = 0; m < M_; m++) { sc[m] = expf(sc[m] - mx); sum += sc[m]; }
    float inv = 1.0f / sum;

    float c0 = 0.0f, c1 = 0.0f;
    #pragma unroll
    for (int m = 0; m < M_; m++) {
        const float* vp = g_v + ((size_t)b * M_ + m) * D_ + h * DK_;
        float a = sc[m] * inv;
        c0 += a * vp[2 * lane];
        c1 += a * vp[2 * lane + 1];
    }
    float* cp = g_ctxh + (size_t)b * D_ + h * DK_;
    cp[2 * lane]     = c0;
    cp[2 * lane + 1] = c1;
}

// ---------------- LayerNorm (warp per row, D = 256) -------------------------
__device__ __forceinline__ void ln_row(const float* x8, int lane,
                                       const float* __restrict__ gm,
                                       const float* __restrict__ bt,
                                       float* __restrict__ yrow)
{
    float s = 0.0f, ss = 0.0f;
    #pragma unroll
    for (int i = 0; i < 8; i++) { s += x8[i]; ss += x8[i] * x8[i]; }
    #pragma unroll
    for (int o = 16; o > 0; o >>= 1) {
        s  += __shfl_xor_sync(0xffffffffu, s,  o);
        ss += __shfl_xor_sync(0xffffffffu, ss, o);
    }
    float mu  = s * (1.0f / 256.0f);
    float var = ss * (1.0f / 256.0f) - mu * mu;
    float inv = rsqrtf(var + 1e-3f);
    float out[8];
    #pragma unroll
    for (int i = 0; i < 8; i++) {
        int d = lane * 8 + i;
        out[i] = (x8[i] - mu) * inv * gm[d] + bt[d];
    }
    *(float4*)(yrow + lane * 8)     = make_float4(out[0], out[1], out[2], out[3]);
    *(float4*)(yrow + lane * 8 + 4) = make_float4(out[4], out[5], out[6], out[7]);
}

__global__ void ln_kernel(const float* __restrict__ x, const float* __restrict__ gm,
                          const float* __restrict__ bt, float* __restrict__ y)
{
    int w    = (blockIdx.x * blockDim.x + threadIdx.x) >> 5;
    int lane = threadIdx.x & 31;
    if (w >= B_) return;
    const float* row = x + (size_t)w * D_;
    float4 v0 = *(const float4*)(row + lane * 8);
    float4 v1 = *(const float4*)(row + lane * 8 + 4);
    float x8[8] = {v0.x, v0.y, v0.z, v0.w, v1.x, v1.y, v1.z, v1.w};
    ln_row(x8, lane, gm, bt, y + (size_t)w * D_);
}

// blend h = (1-alpha)*gru + alpha*ctx_p, then LN -> d_out rows
__global__ void blend_ln_kernel(const float* __restrict__ gm,
                                const float* __restrict__ bt,
                                float* __restrict__ out)
{
    int w    = (blockIdx.x * blockDim.x + threadIdx.x) >> 5;
    int lane = threadIdx.x & 31;
    if (w >= B_) return;
    size_t base = (size_t)w * D_ + lane * 8;
    float x8[8];
    #pragma unroll
    for (int i = 0; i < 8; i++) {
        float a = g_alph[base + i];
        x8[i] = (1.0f - a) * g_gru[base + i] + a * g_ctxp[base + i];
    }
    ln_row(x8, lane, gm, bt, out + (size_t)w * D_);
}

// ---------------- memory shift: out_mem[b, 0:9D] = mem[b, D:10D] ------------
__global__ void memshift_kernel(const float* __restrict__ memflat,
                                float* __restrict__ outmem)
{
    const int per = (M_ - 1) * D_ / 4;   // 576 float4 per row
    int idx = blockIdx.x * blockDim.x + threadIdx.x;
    if (idx >= B_ * per) return;
    int b = idx / per, j = idx - b * per;
    const float4* src = (const float4*)(memflat + (size_t)b * (M_ * D_) + D_);
    float4*       dst = (float4*)(outmem + (size_t)b * (M_ * D_));
    dst[j] = src[j];
}

// ---------------- host ------------------------------------------------------
extern "C" void kernel_launch(void* const* d_in, const int* in_sizes, int n_in,
                              void* d_out, int out_size)
{
    const float* inputs    = (const float*)d_in[0];
    const float* h_prev    = (const float*)d_in[1];
    const float* memflat   = (const float*)d_in[2];
    const float* W_in      = (const float*)d_in[3];
    const float* b_in      = (const float*)d_in[4];
    const float* gru_k     = (const float*)d_in[5];
    const float* gru_rk    = (const float*)d_in[6];
    const float* gru_b     = (const float*)d_in[7];   // (2,768)
    const float* Wq        = (const float*)d_in[8];
    const float* bq        = (const float*)d_in[9];
    const float* Wk        = (const float*)d_in[10];
    const float* bk        = (const float*)d_in[11];
    const float* Wv        = (const float*)d_in[12];
    const float* bv        = (const float*)d_in[13];
    const float* Wo        = (const float*)d_in[14];
    const float* bo        = (const float*)d_in[15];
    const float* g_attn    = (const float*)d_in[16];
    const float* beta_attn = (const float*)d_in[17];
    const float* g_out     = (const float*)d_in[18];
    const float* beta_out  = (const float*)d_in[19];
    const float* W_ctx     = (const float*)d_in[20];
    const float* b_ctx     = (const float*)d_in[21];
    const float* W_gate    = (const float*)d_in[22];
    const float* b_gate    = (const float*)d_in[23];
    const float* W_mem     = (const float*)d_in[24];
    const float* b_mem     = (const float*)d_in[25];
    float* out = (float*)d_out;

    float *zP, *xpP, *hpP, *gruP, *qP, *kP, *vP, *ctxhP, *ctxP, *ctxpP, *alphP;
    cudaGetSymbolAddress((void**)&zP,    g_z);
    cudaGetSymbolAddress((void**)&xpP,   g_xp);
    cudaGetSymbolAddress((void**)&hpP,   g_hp);
    cudaGetSymbolAddress((void**)&gruP,  g_gru);
    cudaGetSymbolAddress((void**)&qP,    g_q);
    cudaGetSymbolAddress((void**)&kP,    g_k);
    cudaGetSymbolAddress((void**)&vP,    g_v);
    cudaGetSymbolAddress((void**)&ctxhP, g_ctxh);
    cudaGetSymbolAddress((void**)&ctxP,  g_ctx);
    cudaGetSymbolAddress((void**)&ctxpP, g_ctxp);
    cudaGetSymbolAddress((void**)&alphP, g_alph);

    const dim3 blk(256);
    const dim3 gB (4, 128);    // 8192x256 GEMM
    const dim3 gB3(12, 128);   // 8192x768 GEMM
    const dim3 gKV(4, 1280);   // 81920x256 GEMM

    // K/V projections (independent, biggest) first
    gemm_kernel<0,false><<<gKV, blk>>>(memflat, nullptr, Wk, bk, kP, 256, 256, 256);
    gemm_kernel<0,false><<<gKV, blk>>>(memflat, nullptr, Wv, bv, vP, 256, 256, 256);

    // z_t, GRU
    gemm_kernel<0,false><<<gB,  blk>>>(inputs, nullptr, W_in,   b_in,       zP,  256, 256, 256);
    gemm_kernel<0,false><<<gB3, blk>>>(zP,     nullptr, gru_k,  gru_b,      xpP, 768, 256, 768);
    gemm_kernel<0,false><<<gB3, blk>>>(h_prev, nullptr, gru_rk, gru_b + 768,hpP, 768, 256, 768);
    gru_kernel<<<(B_ * D_ + 255) / 256, 256>>>(h_prev);

    // attention
    gemm_kernel<0,false><<<gB, blk>>>(gruP, nullptr, Wq, bq, qP, 256, 256, 256);
    attn_kernel<<<(B_ * H_ * 32 + 255) / 256, 256>>>();
    gemm_kernel<0,false><<<gB, blk>>>(ctxhP, nullptr, Wo, bo, ctxP, 256, 256, 256);
    ln_kernel<<<(B_ * 32 + 255) / 256, 256>>>(ctxP, g_attn, beta_attn, ctxP);

    // ctx_p, gate, blend+LN -> h_corr
    gemm_kernel<1,false><<<gB, blk>>>(ctxP, nullptr,  W_ctx,  b_ctx,  ctxpP, 256, 256, 256);
    gemm_kernel<2,true ><<<gB, blk>>>(gruP, ctxpP,    W_gate, b_gate, alphP, 256, 512, 256);
    blend_ln_kernel<<<(B_ * 32 + 255) / 256, 256>>>(g_out, beta_out, out);

    // memory write: shifted copy + new entry in last slot
    memshift_kernel<<<(B_ * 576 + 255) / 256, 256>>>(memflat, out + B_ * D_);
    gemm_kernel<0,false><<<gB, blk>>>(zP, nullptr, W_mem, b_mem,
                                      out + B_ * D_ + (M_ - 1) * D_, 256, 256, M_ * D_);
}

// round 3
// speedup vs baseline: 1.8659x; 1.8659x over previous
#include <cuda_runtime.h>
#include <math.h>
#include <stdint.h>

#define B_  8192
#define D_  256
#define M_  10
#define H_  4
#define DK_ 64

// ---------------- scratch (device globals; no allocation allowed) ----------
__device__ float g_z   [B_*D_];        // z_t
__device__ float g_xp  [B_*3*D_];      // z_t @ gru_k + b0
__device__ float g_hp  [B_*3*D_];      // h_prev @ gru_rk + b1
__device__ float g_gru [B_*D_];        // gru_out
__device__ float g_q   [B_*D_];        // q
__device__ float g_k   [B_*M_*D_];     // k (81920 x 256)
__device__ float g_v   [B_*M_*D_];     // v
__device__ float g_ctxh[B_*D_];        // attention context heads
__device__ float g_ctx [B_*D_];        // context (pre/post LN, in place)
__device__ float g_ctxp[B_*D_];        // tanh(ctx_ln @ W_ctx + b)
__device__ float g_alph[B_*D_];        // gate

__device__ __forceinline__ float sigf(float x) { return 1.0f / (1.0f + expf(-x)); }

__device__ __forceinline__ uint32_t f2tf32(float f) {
    uint32_t u;
    asm("cvt.rna.tf32.f32 %0, %1;" : "=r"(u) : "f"(f));
    return u;
}

__device__ __forceinline__ void mma_tf32(float acc[4], const uint32_t a[4], const uint32_t b[2]) {
    asm volatile(
        "mma.sync.aligned.m16n8k8.row.col.f32.tf32.tf32.f32 "
        "{%0,%1,%2,%3}, {%4,%5,%6,%7}, {%8,%9}, {%0,%1,%2,%3};"
        : "+f"(acc[0]), "+f"(acc[1]), "+f"(acc[2]), "+f"(acc[3])
        : "r"(a[0]), "r"(a[1]), "r"(a[2]), "r"(a[3]), "r"(b[0]), "r"(b[1]));
}

// ---------------- tf32 tensor-core GEMM: C = epi(A @ W + bias) -------------
// A: (Mrows x K) row-major (if DUAL: A = cols [0,256), A2 = cols [256,K))
// W: (K x N) row-major, bias: (N), C row stride ldc.
// Block tile 128x64, BK=32, 256 threads (8 warps, 4x2), warp tile 32x32.
// EPI: 0 = identity, 1 = tanh, 2 = sigmoid
template<int EPI, bool DUAL>
__global__ __launch_bounds__(256)
void gemm_tf32(const float* __restrict__ A, const float* __restrict__ A2,
               const float* __restrict__ W, const float* __restrict__ bias,
               float* __restrict__ C, int N, int K, int ldc)
{
    const int BM = 128, BN = 64, BK = 32;
    __shared__ uint32_t As[BK][BM + 4];   // [k][m], tf32 bits
    __shared__ uint32_t Bs[BK][BN + 4];   // [k][n], tf32 bits

    const int bm   = blockIdx.y * BM;
    const int bn   = blockIdx.x * BN;
    const int tid  = threadIdx.x;
    const int lane = tid & 31;
    const int wid  = tid >> 5;
    const int wm   = (wid & 3) * 32;      // warp m-offset within block
    const int wn   = (wid >> 2) * 32;     // warp n-offset within block
    const int g    = lane >> 2;           // group id (0..7)
    const int q    = lane & 3;            // quad id  (0..3)

    float acc[2][4][4];                   // [m-tile][n-tile][frag]
    #pragma unroll
    for (int t = 0; t < 2; t++)
        #pragma unroll
        for (int j = 0; j < 4; j++)
            #pragma unroll
            for (int e = 0; e < 4; e++) acc[t][j][e] = 0.0f;

    for (int k0 = 0; k0 < K; k0 += BK) {
        // ---- load A tile (128 rows x 32 k), convert to tf32, transpose ----
        #pragma unroll
        for (int i = 0; i < 4; i++) {
            int idx = tid + i * 256;      // 1024 float4 slots
            int row = idx >> 3;
            int c4  = (idx & 7) * 4;
            int gk  = k0 + c4;
            float4 v;
            if (DUAL) {
                v = (gk < 256) ? *(const float4*)&A [(size_t)(bm + row) * 256 + gk]
                               : *(const float4*)&A2[(size_t)(bm + row) * 256 + gk - 256];
            } else {
                v = *(const float4*)&A[(size_t)(bm + row) * K + gk];
            }
            As[c4 + 0][row] = f2tf32(v.x);
            As[c4 + 1][row] = f2tf32(v.y);
            As[c4 + 2][row] = f2tf32(v.z);
            As[c4 + 3][row] = f2tf32(v.w);
        }
        // ---- load W tile (32 k x 64 n), convert to tf32 ----
        #pragma unroll
        for (int i = 0; i < 2; i++) {
            int idx = tid + i * 256;      // 512 float4 slots
            int row = idx >> 4;
            int c4  = (idx & 15) * 4;
            float4 v = *(const float4*)&W[(size_t)(k0 + row) * N + bn + c4];
            Bs[row][c4 + 0] = f2tf32(v.x);
            Bs[row][c4 + 1] = f2tf32(v.y);
            Bs[row][c4 + 2] = f2tf32(v.z);
            Bs[row][c4 + 3] = f2tf32(v.w);
        }
        __syncthreads();

        #pragma unroll
        for (int ks = 0; ks < BK; ks += 8) {
            uint32_t a[2][4];
            #pragma unroll
            for (int t = 0; t < 2; t++) {
                int r = wm + t * 16 + g;
                a[t][0] = As[ks + q    ][r];
                a[t][1] = As[ks + q    ][r + 8];
                a[t][2] = As[ks + q + 4][r];
                a[t][3] = As[ks + q + 4][r + 8];
            }
            uint32_t b[4][2];
            #pragma unroll
            for (int j = 0; j < 4; j++) {
                int c = wn + j * 8 + g;
                b[j][0] = Bs[ks + q    ][c];
                b[j][1] = Bs[ks + q + 4][c];
            }
            #pragma unroll
            for (int t = 0; t < 2; t++)
                #pragma unroll
                for (int j = 0; j < 4; j++)
                    mma_tf32(acc[t][j], a[t], b[j]);
        }
        __syncthreads();
    }

    // ---- epilogue: bias + activation, float2 stores ----
    #pragma unroll
    for (int t = 0; t < 2; t++) {
        #pragma unroll
        for (int j = 0; j < 4; j++) {
            int col = bn + wn + j * 8 + 2 * q;
            float b0 = bias[col], b1 = bias[col + 1];
            #pragma unroll
            for (int h = 0; h < 2; h++) {        // h=0 -> c0,c1 ; h=1 -> c2,c3
                int row = bm + wm + t * 16 + g + h * 8;
                float v0 = acc[t][j][2 * h]     + b0;
                float v1 = acc[t][j][2 * h + 1] + b1;
                if (EPI == 1) { v0 = tanhf(v0); v1 = tanhf(v1); }
                if (EPI == 2) { v0 = sigf(v0);  v1 = sigf(v1);  }
                *(float2*)&C[(size_t)row * ldc + col] = make_float2(v0, v1);
            }
        }
    }
}

// ---------------- GRU elementwise (keras reset_after=True) -----------------
__global__ void gru_kernel(const float* __restrict__ h_prev)
{
    int idx = blockIdx.x * blockDim.x + threadIdx.x;
    if (idx >= B_ * D_) return;
    int b = idx >> 8, d = idx & 255;
    const float* xp = g_xp + (size_t)b * 768;
    const float* hp = g_hp + (size_t)b * 768;
    float z  = sigf(xp[d]       + hp[d]);
    float r  = sigf(xp[256 + d] + hp[256 + d]);
    float hc = tanhf(xp[512 + d] + r * hp[512 + d]);
    float h  = h_prev[idx];
    g_gru[idx] = z * h + (1.0f - z) * hc;
}

// ---------------- attention: one warp per (b, h) ----------------------------
__global__ void attn_kernel()
{
    int gw   = (blockIdx.x * blockDim.x + threadIdx.x) >> 5;
    int lane = threadIdx.x & 31;
    if (gw >= B_ * H_) return;
    int b = gw >> 2;
    int h = gw & 3;

    const float* qp = g_q + (size_t)b * D_ + h * DK_;
    float q0 = qp[2 * lane], q1 = qp[2 * lane + 1];

    float sc[M_];
    #pragma unroll
    for (int m = 0; m < M_; m++) {
        const float* kp = g_k + ((size_t)b * M_ + m) * D_ + h * DK_;
        float p = q0 * kp[2 * lane] + q1 * kp[2 * lane + 1];
        #pragma unroll
        for (int o = 16; o > 0; o >>= 1) p += __shfl_xor_sync(0xffffffffu, p, o);
        sc[m] = p * 0.125f;
    }
    float mx = sc[0];
    #pragma unroll
    for (int m = 1; m < M_; m++) mx = fmaxf(mx, sc[m]);
    float sum = 0.0f;
    #pragma unroll
    for (int m = 0; m < M_; m++) { sc[m] = expf(sc[m] - mx); sum += sc[m]; }
    float inv = 1.0f / sum;

    float c0 = 0.0f, c1 = 0.0f;
    #pragma unroll
    for (int m = 0; m < M_; m++) {
        const float* vp = g_v + ((size_t)b * M_ + m) * D_ + h * DK_;
        float a = sc[m] * inv;
        c0 += a * vp[2 * lane];
        c1 += a * vp[2 * lane + 1];
    }
    float* cp = g_ctxh + (size_t)b * D_ + h * DK_;
    cp[2 * lane]     = c0;
    cp[2 * lane + 1] = c1;
}

// ---------------- LayerNorm (warp per row, D = 256) -------------------------
__device__ __forceinline__ void ln_row(const float* x8, int lane,
                                       const float* __restrict__ gm,
                                       const float* __restrict__ bt,
                                       float* __restrict__ yrow)
{
    float s = 0.0f, ss = 0.0f;
    #pragma unroll
    for (int i = 0; i < 8; i++) { s += x8[i]; ss += x8[i] * x8[i]; }
    #pragma unroll
    for (int o = 16; o > 0; o >>= 1) {
        s  += __shfl_xor_sync(0xffffffffu, s,  o);
        ss += __shfl_xor_sync(0xffffffffu, ss, o);
    }
    float mu  = s * (1.0f / 256.0f);
    float var = ss * (1.0f / 256.0f) - mu * mu;
    float inv = rsqrtf(var + 1e-3f);
    float out[8];
    #pragma unroll
    for (int i = 0; i < 8; i++) {
        int d = lane * 8 + i;
        out[i] = (x8[i] - mu) * inv * gm[d] + bt[d];
    }
    *(float4*)(yrow + lane * 8)     = make_float4(out[0], out[1], out[2], out[3]);
    *(float4*)(yrow + lane * 8 + 4) = make_float4(out[4], out[5], out[6], out[7]);
}

__global__ void ln_kernel(const float* __restrict__ x, const float* __restrict__ gm,
                          const float* __restrict__ bt, float* __restrict__ y)
{
    int w    = (blockIdx.x * blockDim.x + threadIdx.x) >> 5;
    int lane = threadIdx.x & 31;
    if (w >= B_) return;
    const float* row = x + (size_t)w * D_;
    float4 v0 = *(const float4*)(row + lane * 8);
    float4 v1 = *(const float4*)(row + lane * 8 + 4);
    float x8[8] = {v0.x, v0.y, v0.z, v0.w, v1.x, v1.y, v1.z, v1.w};
    ln_row(x8, lane, gm, bt, y + (size_t)w * D_);
}

__global__ void blend_ln_kernel(const float* __restrict__ gm,
                                const float* __restrict__ bt,
                                float* __restrict__ out)
{
    int w    = (blockIdx.x * blockDim.x + threadIdx.x) >> 5;
    int lane = threadIdx.x & 31;
    if (w >= B_) return;
    size_t base = (size_t)w * D_ + lane * 8;
    float x8[8];
    #pragma unroll
    for (int i = 0; i < 8; i++) {
        float a = g_alph[base + i];
        x8[i] = (1.0f - a) * g_gru[base + i] + a * g_ctxp[base + i];
    }
    ln_row(x8, lane, gm, bt, out + (size_t)w * D_);
}

// ---------------- memory shift: out_mem[b, 0:9D] = mem[b, D:10D] ------------
__global__ void memshift_kernel(const float* __restrict__ memflat,
                                float* __restrict__ outmem)
{
    const int per = (M_ - 1) * D_ / 4;   // 576 float4 per row
    int idx = blockIdx.x * blockDim.x + threadIdx.x;
    if (idx >= B_ * per) return;
    int b = idx / per, j = idx - b * per;
    const float4* src = (const float4*)(memflat + (size_t)b * (M_ * D_) + D_);
    float4*       dst = (float4*)(outmem + (size_t)b * (M_ * D_));
    dst[j] = src[j];
}

// ---------------- host ------------------------------------------------------
extern "C" void kernel_launch(void* const* d_in, const int* in_sizes, int n_in,
                              void* d_out, int out_size)
{
    const float* inputs    = (const float*)d_in[0];
    const float* h_prev    = (const float*)d_in[1];
    const float* memflat   = (const float*)d_in[2];
    const float* W_in      = (const float*)d_in[3];
    const float* b_in      = (const float*)d_in[4];
    const float* gru_k     = (const float*)d_in[5];
    const float* gru_rk    = (const float*)d_in[6];
    const float* gru_b     = (const float*)d_in[7];
    const float* Wq        = (const float*)d_in[8];
    const float* bq        = (const float*)d_in[9];
    const float* Wk        = (const float*)d_in[10];
    const float* bk        = (const float*)d_in[11];
    const float* Wv        = (const float*)d_in[12];
    const float* bv        = (const float*)d_in[13];
    const float* Wo        = (const float*)d_in[14];
    const float* bo        = (const float*)d_in[15];
    const float* g_attn    = (const float*)d_in[16];
    const float* beta_attn = (const float*)d_in[17];
    const float* g_out     = (const float*)d_in[18];
    const float* beta_out  = (const float*)d_in[19];
    const float* W_ctx     = (const float*)d_in[20];
    const float* b_ctx     = (const float*)d_in[21];
    const float* W_gate    = (const float*)d_in[22];
    const float* b_gate    = (const float*)d_in[23];
    const float* W_mem     = (const float*)d_in[24];
    const float* b_mem     = (const float*)d_in[25];
    float* out = (float*)d_out;

    float *zP, *xpP, *hpP, *gruP, *qP, *kP, *vP, *ctxhP, *ctxP, *ctxpP, *alphP;
    cudaGetSymbolAddress((void**)&zP,    g_z);
    cudaGetSymbolAddress((void**)&xpP,   g_xp);
    cudaGetSymbolAddress((void**)&hpP,   g_hp);
    cudaGetSymbolAddress((void**)&gruP,  g_gru);
    cudaGetSymbolAddress((void**)&qP,    g_q);
    cudaGetSymbolAddress((void**)&kP,    g_k);
    cudaGetSymbolAddress((void**)&vP,    g_v);
    cudaGetSymbolAddress((void**)&ctxhP, g_ctxh);
    cudaGetSymbolAddress((void**)&ctxP,  g_ctx);
    cudaGetSymbolAddress((void**)&ctxpP, g_ctxp);
    cudaGetSymbolAddress((void**)&alphP, g_alph);

    const dim3 blk(256);
    const dim3 gB (4, 64);     // 8192 x 256   (N=256 -> 4 blocks in x)
    const dim3 gB3(12, 64);    // 8192 x 768   (N=768 -> 12)
    const dim3 gGate(4, 64);   // 8192 x 256, K=512 (gate: N=256 -> 4!)
    const dim3 gKV(4, 640);    // 81920 x 256

    // K/V projections (independent, biggest) first
    gemm_tf32<0,false><<<gKV, blk>>>(memflat, nullptr, Wk, bk, kP, 256, 256, 256);
    gemm_tf32<0,false><<<gKV, blk>>>(memflat, nullptr, Wv, bv, vP, 256, 256, 256);

    // z_t, GRU
    gemm_tf32<0,false><<<gB,  blk>>>(inputs, nullptr, W_in,   b_in,        zP,  256, 256, 256);
    gemm_tf32<0,false><<<gB3, blk>>>(zP,     nullptr, gru_k,  gru_b,       xpP, 768, 256, 768);
    gemm_tf32<0,false><<<gB3, blk>>>(h_prev, nullptr, gru_rk, gru_b + 768, hpP, 768, 256, 768);
    gru_kernel<<<(B_ * D_ + 255) / 256, 256>>>(h_prev);

    // attention
    gemm_tf32<0,false><<<gB, blk>>>(gruP, nullptr, Wq, bq, qP, 256, 256, 256);
    attn_kernel<<<(B_ * H_ * 32 + 255) / 256, 256>>>();
    gemm_tf32<0,false><<<gB, blk>>>(ctxhP, nullptr, Wo, bo, ctxP, 256, 256, 256);
    ln_kernel<<<(B_ * 32 + 255) / 256, 256>>>(ctxP, g_attn, beta_attn, ctxP);

    // ctx_p, gate, blend+LN -> h_corr
    gemm_tf32<1,false><<<gB,    blk>>>(ctxP, nullptr, W_ctx,  b_ctx,  ctxpP, 256, 256, 256);
    gemm_tf32<2,true ><<<gGate, blk>>>(gruP, ctxpP,   W_gate, b_gate, alphP, 256, 512, 256);
    blend_ln_kernel<<<(B_ * 32 + 255) / 256, 256>>>(g_out, beta_out, out);

    // memory write: shifted copy + new entry in last slot
    memshift_kernel<<<(B_ * 576 + 255) / 256, 256>>>(memflat, out + B_ * D_);
    gemm_tf32<0,false><<<gB, blk>>>(zP, nullptr, W_mem, b_mem,
                                    out + B_ * D_ + (M_ - 1) * D_, 256, 256, M_ * D_);
}